// round 5
// baseline (speedup 1.0000x reference)
#include <cuda_runtime.h>
#include <cuda_bf16.h>
#include <math.h>
#include <stdint.h>

#define S_LEN 2048
#define DIMN  2048
#define NH    16
#define NKV   4
#define HD    128
#define ROWS  4096   // B*S

// ---------------- scratch (device globals; no allocation allowed) ----------
__device__ __nv_bfloat16 g_xn_h[ROWS * DIMN];
__device__ __nv_bfloat16 g_xn_l[ROWS * DIMN];
__device__ __nv_bfloat16 g_wq_h[DIMN * DIMN];
__device__ __nv_bfloat16 g_wq_l[DIMN * DIMN];
__device__ __nv_bfloat16 g_wk_h[512 * DIMN];
__device__ __nv_bfloat16 g_wk_l[512 * DIMN];
__device__ __nv_bfloat16 g_wv_h[512 * DIMN];
__device__ __nv_bfloat16 g_wv_l[512 * DIMN];
__device__ __nv_bfloat16 g_wo_h[DIMN * DIMN];
__device__ __nv_bfloat16 g_wo_l[DIMN * DIMN];
__device__ __nv_bfloat16 g_qh[ROWS * DIMN];  // roped+scaled Q hi/lo
__device__ __nv_bfloat16 g_ql[ROWS * DIMN];
__device__ __nv_bfloat16 g_kh[ROWS * 512];   // roped K hi/lo
__device__ __nv_bfloat16 g_kl[ROWS * 512];
__device__ __nv_bfloat16 g_vh[ROWS * 512];   // V hi/lo
__device__ __nv_bfloat16 g_vl[ROWS * 512];
__device__ float g_ao[ROWS * DIMN];   // attention output (B,S,16,128)
__device__ int   g_cs[2 * S_LEN];     // per-batch inclusive cumsum of labels

// ---------------- helpers ----------------------------------------------------
__device__ __forceinline__ uint32_t smem_to_u32(const void* p) {
    uint32_t a;
    asm("{ .reg .u64 t; cvta.to.shared.u64 t, %1; cvt.u32.u64 %0, t; }" : "=r"(a) : "l"(p));
    return a;
}
__device__ __forceinline__ void ldmx4(uint32_t* r, uint32_t addr) {
    asm volatile("ldmatrix.sync.aligned.m8n8.x4.shared.b16 {%0,%1,%2,%3}, [%4];"
        : "=r"(r[0]), "=r"(r[1]), "=r"(r[2]), "=r"(r[3]) : "r"(addr));
}
__device__ __forceinline__ void ldmx2(uint32_t* r, uint32_t addr) {
    asm volatile("ldmatrix.sync.aligned.m8n8.x2.shared.b16 {%0,%1}, [%2];"
        : "=r"(r[0]), "=r"(r[1]) : "r"(addr));
}
__device__ __forceinline__ void ldmx4t(uint32_t* r, uint32_t addr) {
    asm volatile("ldmatrix.sync.aligned.m8n8.x4.trans.shared.b16 {%0,%1,%2,%3}, [%4];"
        : "=r"(r[0]), "=r"(r[1]), "=r"(r[2]), "=r"(r[3]) : "r"(addr));
}
__device__ __forceinline__ void mma16816(float* c, const uint32_t* a, const uint32_t* b) {
    asm volatile(
        "mma.sync.aligned.m16n8k16.row.col.f32.bf16.bf16.f32 "
        "{%0,%1,%2,%3}, {%4,%5,%6,%7}, {%8,%9}, {%0,%1,%2,%3};"
        : "+f"(c[0]), "+f"(c[1]), "+f"(c[2]), "+f"(c[3])
        : "r"(a[0]), "r"(a[1]), "r"(a[2]), "r"(a[3]), "r"(b[0]), "r"(b[1]));
}
__device__ __forceinline__ void cp16(uint32_t d, const void* s) {
    asm volatile("cp.async.ca.shared.global [%0], [%1], 16;" :: "r"(d), "l"(s));
}
__device__ __forceinline__ void pack_hilo(float x, float y, uint32_t& h, uint32_t& l) {
    __nv_bfloat162 hb = __floats2bfloat162_rn(x, y);
    float rx = x - __bfloat162float(hb.x);
    float ry = y - __bfloat162float(hb.y);
    __nv_bfloat162 lb = __floats2bfloat162_rn(rx, ry);
    h = *(uint32_t*)&hb;
    l = *(uint32_t*)&lb;
}

// ---------------- cumsum of seizure labels (per batch) ---------------------
__global__ void cumsum_kernel(const int* __restrict__ labels) {
    __shared__ int bufA[S_LEN], bufB[S_LEN];
    int b = blockIdx.x;
    for (int i = threadIdx.x; i < S_LEN; i += blockDim.x)
        bufA[i] = labels[b * S_LEN + i];
    __syncthreads();
    int* src = bufA; int* dst = bufB;
    for (int off = 1; off < S_LEN; off <<= 1) {
        for (int i = threadIdx.x; i < S_LEN; i += blockDim.x)
            dst[i] = src[i] + (i >= off ? src[i - off] : 0);
        __syncthreads();
        int* t = src; src = dst; dst = t;
    }
    for (int i = threadIdx.x; i < S_LEN; i += blockDim.x)
        g_cs[b * S_LEN + i] = src[i];
}

// ---------------- bf16 split helpers ---------------------------------------
__device__ __forceinline__ void split4(float4 v, uint32_t& h01, uint32_t& h23,
                                       uint32_t& l01, uint32_t& l23) {
    pack_hilo(v.x, v.y, h01, l01);
    pack_hilo(v.z, v.w, h23, l23);
}

__global__ void split_kernel(const float* __restrict__ in,
                             __nv_bfloat16* __restrict__ hi,
                             __nv_bfloat16* __restrict__ lo, int n4) {
    int i = blockIdx.x * blockDim.x + threadIdx.x;
    if (i >= n4) return;
    float4 v = ((const float4*)in)[i];
    uint32_t h01, h23, l01, l23;
    split4(v, h01, h23, l01, l23);
    *(uint2*)(hi + (size_t)i * 4) = make_uint2(h01, h23);
    *(uint2*)(lo + (size_t)i * 4) = make_uint2(l01, l23);
}

// ---------------- layernorm -> bf16 hi/lo -----------------------------------
__global__ void ln_kernel(const float* __restrict__ in, const float* __restrict__ w,
                          const float* __restrict__ bvec,
                          __nv_bfloat16* __restrict__ oh, __nv_bfloat16* __restrict__ ol) {
    int row = blockIdx.x;
    const float* x = in + (size_t)row * DIMN;
    int tid = threadIdx.x;

    float4 v0 = *(const float4*)(x + tid * 4);
    float4 v1 = *(const float4*)(x + 1024 + tid * 4);
    float s  = v0.x + v0.y + v0.z + v0.w + v1.x + v1.y + v1.z + v1.w;
    float ss = v0.x*v0.x + v0.y*v0.y + v0.z*v0.z + v0.w*v0.w
             + v1.x*v1.x + v1.y*v1.y + v1.z*v1.z + v1.w*v1.w;
    #pragma unroll
    for (int off = 16; off; off >>= 1) {
        s  += __shfl_xor_sync(0xffffffffu, s,  off);
        ss += __shfl_xor_sync(0xffffffffu, ss, off);
    }
    __shared__ float rs[8], rss[8];
    __shared__ float s_mu, s_rstd;
    int wid = tid >> 5, lane = tid & 31;
    if (!lane) { rs[wid] = s; rss[wid] = ss; }
    __syncthreads();
    if (tid == 0) {
        float S = 0.f, SS = 0.f;
        #pragma unroll
        for (int i = 0; i < 8; ++i) { S += rs[i]; SS += rss[i]; }
        float mu = S / DIMN;
        s_mu = mu;
        s_rstd = rsqrtf(SS / DIMN - mu * mu + 1e-5f);
    }
    __syncthreads();
    float mu = s_mu, rstd = s_rstd;

    size_t base = (size_t)row * DIMN;
    #pragma unroll
    for (int half = 0; half < 2; ++half) {
        int off = half * 1024 + tid * 4;
        float4 v = half ? v1 : v0;
        float4 w4 = *(const float4*)(w + off);
        float4 b4 = *(const float4*)(bvec + off);
        float4 r;
        r.x = (v.x - mu) * rstd * w4.x + b4.x;
        r.y = (v.y - mu) * rstd * w4.y + b4.y;
        r.z = (v.z - mu) * rstd * w4.z + b4.z;
        r.w = (v.w - mu) * rstd * w4.w + b4.w;
        uint32_t h01, h23, l01, l23;
        split4(r, h01, h23, l01, l23);
        *(uint2*)(oh + base + off) = make_uint2(h01, h23);
        *(uint2*)(ol + base + off) = make_uint2(l01, l23);
    }
}

// ---------------- mma.sync GEMM: C[M,N] = A[M,K] * B[N,K]^T -----------------
// mode 0: fp32 -> C.  mode 1: rope(pairs)+scale -> bf16 hi/lo Oh/Ol.
// mode 2: split only -> Oh/Ol.
#define PITCH 80
#define TILE_B (128 * PITCH)
#define STAGE_B (4 * TILE_B)

__device__ __forceinline__ void cp_tile(uint32_t sdst, const __nv_bfloat16* __restrict__ g,
                                        int row0, int K, int k0) {
    int tid = threadIdx.x;
    const char* gb = (const char*)(g + (size_t)row0 * K + k0);
    size_t rb = (size_t)K * 2;
    #pragma unroll
    for (int j = 0; j < 2; ++j) {
        int lin = j * 256 + tid;
        int r = lin >> 2, c = lin & 3;
        cp16(sdst + r * PITCH + c * 16, gb + (size_t)r * rb + c * 16);
    }
}

__global__ __launch_bounds__(256)
void mma_gemm(const __nv_bfloat16* __restrict__ Ah, const __nv_bfloat16* __restrict__ Al,
              const __nv_bfloat16* __restrict__ Bh, const __nv_bfloat16* __restrict__ Bl,
              float* __restrict__ C,
              __nv_bfloat16* __restrict__ Oh, __nv_bfloat16* __restrict__ Ol,
              const float* __restrict__ fr, int mode, float scale,
              int M, int N, int K) {
    extern __shared__ char sm[];
    uint32_t sb = smem_to_u32(sm);
    int tid = threadIdx.x, lane = tid & 31, wid = tid >> 5;
    int wm = wid & 1, wn = wid >> 1;
    int row0 = blockIdx.y * 128, col0 = blockIdx.x * 128;

    float acc[4][4][4];
    #pragma unroll
    for (int i = 0; i < 4; ++i)
        #pragma unroll
        for (int j = 0; j < 4; ++j)
            #pragma unroll
            for (int q = 0; q < 4; ++q) acc[i][j][q] = 0.f;

    const int nst = K >> 5;

    cp_tile(sb,              Ah, row0, K, 0);
    cp_tile(sb + TILE_B,     Al, row0, K, 0);
    cp_tile(sb + 2 * TILE_B, Bh, col0, K, 0);
    cp_tile(sb + 3 * TILE_B, Bl, col0, K, 0);
    asm volatile("cp.async.commit_group;" ::: "memory");

    for (int i = 0; i < nst; ++i) {
        if (i + 1 < nst) {
            uint32_t st = sb + ((i + 1) & 1) * STAGE_B;
            int k0 = (i + 1) << 5;
            cp_tile(st,              Ah, row0, K, k0);
            cp_tile(st + TILE_B,     Al, row0, K, k0);
            cp_tile(st + 2 * TILE_B, Bh, col0, K, k0);
            cp_tile(st + 3 * TILE_B, Bl, col0, K, k0);
            asm volatile("cp.async.commit_group;" ::: "memory");
            asm volatile("cp.async.wait_group 1;" ::: "memory");
        } else {
            asm volatile("cp.async.wait_group 0;" ::: "memory");
        }
        __syncthreads();

        uint32_t st = sb + (i & 1) * STAGE_B;
        #pragma unroll
        for (int ks = 0; ks < 2; ++ks) {
            uint32_t ah[4][4], al[4][4], bh[4][2], bl[4][2];
            uint32_t abase = st + (wm * 64 + (lane & 15)) * PITCH
                           + (ks * 2 + (lane >> 4)) * 16;
            #pragma unroll
            for (int mi = 0; mi < 4; ++mi) ldmx4(ah[mi], abase + mi * 16 * PITCH);
            #pragma unroll
            for (int mi = 0; mi < 4; ++mi) ldmx4(al[mi], abase + TILE_B + mi * 16 * PITCH);
            uint32_t bbase = st + 2 * TILE_B + (wn * 32 + (lane & 7)) * PITCH
                           + ((lane >> 3) & 1) * 16 + ks * 32;
            #pragma unroll
            for (int ni = 0; ni < 4; ++ni) ldmx2(bh[ni], bbase + ni * 8 * PITCH);
            #pragma unroll
            for (int ni = 0; ni < 4; ++ni) ldmx2(bl[ni], bbase + TILE_B + ni * 8 * PITCH);
            #pragma unroll
            for (int mi = 0; mi < 4; ++mi)
                #pragma unroll
                for (int ni = 0; ni < 4; ++ni) {
                    mma16816(acc[mi][ni], ah[mi], bh[ni]);
                    mma16816(acc[mi][ni], ah[mi], bl[ni]);
                    mma16816(acc[mi][ni], al[mi], bh[ni]);
                }
        }
        __syncthreads();
    }

    int mrow = row0 + wm * 64 + (lane >> 2);
    int ncol = col0 + wn * 32 + (lane & 3) * 2;

    if (mode == 0) {
        #pragma unroll
        for (int mi = 0; mi < 4; ++mi)
            #pragma unroll
            for (int ni = 0; ni < 4; ++ni) {
                float* p0 = C + (size_t)(mrow + mi * 16) * N + ncol + ni * 8;
                float* p1 = C + (size_t)(mrow + mi * 16 + 8) * N + ncol + ni * 8;
                *(float2*)p0 = make_float2(acc[mi][ni][0], acc[mi][ni][1]);
                *(float2*)p1 = make_float2(acc[mi][ni][2], acc[mi][ni][3]);
            }
    } else {
        #pragma unroll
        for (int mi = 0; mi < 4; ++mi)
            #pragma unroll
            for (int ni = 0; ni < 4; ++ni) {
                int col = ncol + ni * 8;
                int r0 = mrow + mi * 16, r1 = r0 + 8;
                float x0 = acc[mi][ni][0], y0 = acc[mi][ni][1];
                float x1 = acc[mi][ni][2], y1 = acc[mi][ni][3];
                if (mode == 1) {
                    int fi = (col & 127) >> 1;
                    int s0 = r0 & (S_LEN - 1), s1 = r1 & (S_LEN - 1);
                    float c0 = fr[(s0 * 64 + fi) * 2], n0 = fr[(s0 * 64 + fi) * 2 + 1];
                    float c1 = fr[(s1 * 64 + fi) * 2], n1 = fr[(s1 * 64 + fi) * 2 + 1];
                    float tx0 = (x0 * c0 - y0 * n0) * scale;
                    float ty0 = (x0 * n0 + y0 * c0) * scale;
                    float tx1 = (x1 * c1 - y1 * n1) * scale;
                    float ty1 = (x1 * n1 + y1 * c1) * scale;
                    x0 = tx0; y0 = ty0; x1 = tx1; y1 = ty1;
                }
                uint32_t h0, l0, h1, l1;
                pack_hilo(x0, y0, h0, l0);
                pack_hilo(x1, y1, h1, l1);
                *(uint32_t*)(Oh + (size_t)r0 * N + col) = h0;
                *(uint32_t*)(Ol + (size_t)r0 * N + col) = l0;
                *(uint32_t*)(Oh + (size_t)r1 * N + col) = h1;
                *(uint32_t*)(Ol + (size_t)r1 * N + col) = l1;
            }
    }
}

// ---------------- tensor-core flash attention --------------------------------
// CTA: 128 q-rows, 8 warps (16 rows each), 256 threads. K-tiles of 64, 2 stages.
#define APITCH 272
#define ATILE  (64 * APITCH)     // 17408 bytes (64-row KV tile)
#define QTILE  (128 * APITCH)    // 34816 bytes (128-row Q tile)

__device__ __forceinline__ void cp_kv(uint32_t dst, const __nv_bfloat16* __restrict__ g,
                                      int b, int kvh, int row0) {
    int tid = threadIdx.x;
    #pragma unroll
    for (int j = 0; j < 4; ++j) {
        int lin = j * 256 + tid;
        int r = lin >> 4, c = lin & 15;
        const __nv_bfloat16* s = g + (((size_t)(b * S_LEN + row0 + r)) * NKV + kvh) * HD + c * 8;
        cp16(dst + r * APITCH + c * 16, s);
    }
}

__global__ __launch_bounds__(256, 1)
void attn_kernel() {
    extern __shared__ char asm_[];
    uint32_t sb = smem_to_u32(asm_);
    const uint32_t smQh = sb;
    const uint32_t smQl = sb + QTILE;
    const uint32_t smKV = sb + 2 * QTILE;   // stage s: Kh,Kl,Vh,Vl each ATILE

    const int tid = threadIdx.x;
    const int lane = tid & 31, wid = tid >> 5;
    const int gid = lane >> 2, tig = lane & 3;
    const int q0 = blockIdx.x * 128;
    const int h  = blockIdx.y;
    const int b  = blockIdx.z;
    const int kvh = h >> 2;
    const int m0 = wid * 16;
    const int nkt = 2 * (blockIdx.x + 1);

    // ---- prologue: Q tiles + first two KV stages ----
    #pragma unroll
    for (int j = 0; j < 8; ++j) {
        int lin = j * 256 + tid;
        int r = lin >> 4, c = lin & 15;
        size_t go = (((size_t)(b * S_LEN + q0 + r)) * NH + h) * HD + c * 8;
        cp16(smQh + r * APITCH + c * 16, g_qh + go);
        cp16(smQl + r * APITCH + c * 16, g_ql + go);
    }
    cp_kv(smKV,             g_kh, b, kvh, 0);
    cp_kv(smKV + ATILE,     g_kl, b, kvh, 0);
    cp_kv(smKV + 2 * ATILE, g_vh, b, kvh, 0);
    cp_kv(smKV + 3 * ATILE, g_vl, b, kvh, 0);
    asm volatile("cp.async.commit_group;" ::: "memory");
    {
        uint32_t st = smKV + 4 * ATILE;
        cp_kv(st,             g_kh, b, kvh, 64);
        cp_kv(st + ATILE,     g_kl, b, kvh, 64);
        cp_kv(st + 2 * ATILE, g_vh, b, kvh, 64);
        cp_kv(st + 3 * ATILE, g_vl, b, kvh, 64);
        asm volatile("cp.async.commit_group;" ::: "memory");
    }

    const int qg0 = q0 + m0 + gid;   // row for c0,c1
    const int qg1 = qg0 + 8;         // row for c2,c3
    const int qmax = q0 + m0 + 15;   // max row this warp owns
    const int csq0 = (qg0 > 0) ? g_cs[b * S_LEN + qg0 - 1] : 0;
    const int csq1 = g_cs[b * S_LEN + qg1 - 1];

    float oacc[16][4];
    #pragma unroll
    for (int d = 0; d < 16; ++d)
        #pragma unroll
        for (int q = 0; q < 4; ++q) oacc[d][q] = 0.f;
    float mrow0 = -1e30f, mrow1 = -1e30f, lrow0 = 0.f, lrow1 = 0.f;

    for (int it = 0; it < nkt; ++it) {
        const int k0 = it * 64;
        if (it + 1 < nkt) asm volatile("cp.async.wait_group 1;" ::: "memory");
        else              asm volatile("cp.async.wait_group 0;" ::: "memory");
        __syncthreads();

        if (k0 <= qmax) {   // warp-level causal tile skip
            const uint32_t st  = smKV + (it & 1) * 4 * ATILE;
            const uint32_t sKh = st, sKl = st + ATILE, sVh = st + 2 * ATILE, sVl = st + 3 * ATILE;

            // ---- S = Q K^T ----
            float sacc[8][4];
            #pragma unroll
            for (int j = 0; j < 8; ++j)
                #pragma unroll
                for (int q = 0; q < 4; ++q) sacc[j][q] = 0.f;

            const uint32_t qoff = (m0 + (lane & 15)) * APITCH + (lane >> 4) * 16;
            const uint32_t koff = (lane & 7) * APITCH + ((lane >> 3) & 1) * 16;
            #pragma unroll
            for (int kk = 0; kk < 8; ++kk) {
                uint32_t qh[4], ql[4];
                ldmx4(qh, smQh + qoff + kk * 32);
                ldmx4(ql, smQl + qoff + kk * 32);
                #pragma unroll
                for (int j = 0; j < 8; ++j) {
                    uint32_t kh[2], kl[2];
                    ldmx2(kh, sKh + koff + j * 8 * APITCH + kk * 32);
                    ldmx2(kl, sKl + koff + j * 8 * APITCH + kk * 32);
                    mma16816(sacc[j], qh, kh);
                    mma16816(sacc[j], qh, kl);
                    mma16816(sacc[j], ql, kh);
                }
            }

            // ---- bias (pre-ictal) ----
            if (k0 + 73 >= q0 + m0) {
                #pragma unroll
                for (int j = 0; j < 8; ++j) {
                    int kg0 = k0 + j * 8 + tig * 2;
                    int kg1 = kg0 + 1;
                    int bi0 = kg0 + 10; if (bi0 > S_LEN - 1) bi0 = S_LEN - 1;
                    int bi1 = kg1 + 10; if (bi1 > S_LEN - 1) bi1 = S_LEN - 1;
                    int ck0 = g_cs[b * S_LEN + bi0];
                    int ck1 = g_cs[b * S_LEN + bi1];
                    if (kg0 + 10 >= qg0 && ck0 - csq0 > 0) sacc[j][0] += 2.0f;
                    if (kg1 + 10 >= qg0 && ck1 - csq0 > 0) sacc[j][1] += 2.0f;
                    if (kg0 + 10 >= qg1 && ck0 - csq1 > 0) sacc[j][2] += 2.0f;
                    if (kg1 + 10 >= qg1 && ck1 - csq1 > 0) sacc[j][3] += 2.0f;
                }
            }
            // ---- causal mask ----
            if (k0 + 63 > qg0) {
                #pragma unroll
                for (int j = 0; j < 8; ++j) {
                    int kg0 = k0 + j * 8 + tig * 2;
                    int kg1 = kg0 + 1;
                    if (kg0 > qg0) sacc[j][0] = -1e9f;
                    if (kg1 > qg0) sacc[j][1] = -1e9f;
                    if (kg0 > qg1) sacc[j][2] = -1e9f;
                    if (kg1 > qg1) sacc[j][3] = -1e9f;
                }
            }

            // ---- online softmax ----
            float mx0 = -1e30f, mx1 = -1e30f;
            #pragma unroll
            for (int j = 0; j < 8; ++j) {
                mx0 = fmaxf(mx0, fmaxf(sacc[j][0], sacc[j][1]));
                mx1 = fmaxf(mx1, fmaxf(sacc[j][2], sacc[j][3]));
            }
            mx0 = fmaxf(mx0, __shfl_xor_sync(0xffffffffu, mx0, 1));
            mx0 = fmaxf(mx0, __shfl_xor_sync(0xffffffffu, mx0, 2));
            mx1 = fmaxf(mx1, __shfl_xor_sync(0xffffffffu, mx1, 1));
            mx1 = fmaxf(mx1, __shfl_xor_sync(0xffffffffu, mx1, 2));
            float mn0 = fmaxf(mrow0, mx0), mn1 = fmaxf(mrow1, mx1);
            float a0 = __expf(mrow0 - mn0), a1 = __expf(mrow1 - mn1);
            mrow0 = mn0; mrow1 = mn1;
            float sum0 = 0.f, sum1 = 0.f;
            #pragma unroll
            for (int j = 0; j < 8; ++j) {
                sacc[j][0] = __expf(sacc[j][0] - mn0); sum0 += sacc[j][0];
                sacc[j][1] = __expf(sacc[j][1] - mn0); sum0 += sacc[j][1];
                sacc[j][2] = __expf(sacc[j][2] - mn1); sum1 += sacc[j][2];
                sacc[j][3] = __expf(sacc[j][3] - mn1); sum1 += sacc[j][3];
            }
            sum0 += __shfl_xor_sync(0xffffffffu, sum0, 1);
            sum0 += __shfl_xor_sync(0xffffffffu, sum0, 2);
            sum1 += __shfl_xor_sync(0xffffffffu, sum1, 1);
            sum1 += __shfl_xor_sync(0xffffffffu, sum1, 2);
            lrow0 = lrow0 * a0 + sum0;
            lrow1 = lrow1 * a1 + sum1;
            #pragma unroll
            for (int d = 0; d < 16; ++d) {
                oacc[d][0] *= a0; oacc[d][1] *= a0;
                oacc[d][2] *= a1; oacc[d][3] *= a1;
            }

            // ---- P fragments (hi/lo) ----
            uint32_t aph[4][4], apl[4][4];
            #pragma unroll
            for (int t = 0; t < 4; ++t) {
                int j0 = 2 * t, j1 = 2 * t + 1;
                pack_hilo(sacc[j0][0], sacc[j0][1], aph[t][0], apl[t][0]);
                pack_hilo(sacc[j0][2], sacc[j0][3], aph[t][1], apl[t][1]);
                pack_hilo(sacc[j1][0], sacc[j1][1], aph[t][2], apl[t][2]);
                pack_hilo(sacc[j1][2], sacc[j1][3], aph[t][3], apl[t][3]);
            }

            // ---- O += P V ----
            const uint32_t voff = (lane & 15) * APITCH + (lane >> 4) * 16;
            #pragma unroll
            for (int t = 0; t < 4; ++t) {
                #pragma unroll
                for (int dn2 = 0; dn2 < 8; ++dn2) {
                    uint32_t vh[4], vl[4];
                    uint32_t va = voff + t * 16 * APITCH + dn2 * 32;
                    ldmx4t(vh, sVh + va);
                    ldmx4t(vl, sVl + va);
                    mma16816(oacc[2 * dn2],     aph[t], vh);
                    mma16816(oacc[2 * dn2],     aph[t], vl);
                    mma16816(oacc[2 * dn2],     apl[t], vh);
                    mma16816(oacc[2 * dn2 + 1], aph[t], vh + 2);
                    mma16816(oacc[2 * dn2 + 1], aph[t], vl + 2);
                    mma16816(oacc[2 * dn2 + 1], apl[t], vh + 2);
                }
            }
        }
        __syncthreads();

        // prefetch stage it+2 into the buffer just consumed
        if (it + 2 < nkt) {
            uint32_t pst = smKV + (it & 1) * 4 * ATILE;
            int row0 = (it + 2) * 64;
            cp_kv(pst,             g_kh, b, kvh, row0);
            cp_kv(pst + ATILE,     g_kl, b, kvh, row0);
            cp_kv(pst + 2 * ATILE, g_vh, b, kvh, row0);
            cp_kv(pst + 3 * ATILE, g_vl, b, kvh, row0);
            asm volatile("cp.async.commit_group;" ::: "memory");
        }
    }

    // ---- epilogue ----
    float il0 = 1.0f / lrow0, il1 = 1.0f / lrow1;
    size_t b0 = (((size_t)(b * S_LEN + qg0)) * NH + h) * HD + tig * 2;
    size_t b1 = (((size_t)(b * S_LEN + qg1)) * NH + h) * HD + tig * 2;
    #pragma unroll
    for (int d = 0; d < 16; ++d) {
        *(float2*)(g_ao + b0 + d * 8) = make_float2(oacc[d][0] * il0, oacc[d][1] * il0);
        *(float2*)(g_ao + b1 + d * 8) = make_float2(oacc[d][2] * il1, oacc[d][3] * il1);
    }
}

// ---------------- launch ----------------------------------------------------
extern "C" void kernel_launch(void* const* d_in, const int* in_sizes, int n_in,
                              void* d_out, int out_size) {
    const float* x      = (const float*)d_in[0];
    const float* freqs  = (const float*)d_in[2];
    const int*   labels = (const int*)d_in[4];
    const float* wq     = (const float*)d_in[5];
    const float* wk     = (const float*)d_in[6];
    const float* wv     = (const float*)d_in[7];
    const float* wo     = (const float*)d_in[8];
    const float* ln1w   = (const float*)d_in[9];
    const float* ln1b   = (const float*)d_in[10];
    const float* ln2w   = (const float*)d_in[11];
    const float* ln2b   = (const float*)d_in[12];
    float* out = (float*)d_out;

    __nv_bfloat16 *xnh, *xnl, *wqh, *wql, *wkh, *wkl, *wvh, *wvl, *woh, *wol;
    __nv_bfloat16 *qh, *ql, *kh, *kl, *vh, *vl;
    float *ao;
    cudaGetSymbolAddress((void**)&xnh, g_xn_h);
    cudaGetSymbolAddress((void**)&xnl, g_xn_l);
    cudaGetSymbolAddress((void**)&wqh, g_wq_h);
    cudaGetSymbolAddress((void**)&wql, g_wq_l);
    cudaGetSymbolAddress((void**)&wkh, g_wk_h);
    cudaGetSymbolAddress((void**)&wkl, g_wk_l);
    cudaGetSymbolAddress((void**)&wvh, g_wv_h);
    cudaGetSymbolAddress((void**)&wvl, g_wv_l);
    cudaGetSymbolAddress((void**)&woh, g_wo_h);
    cudaGetSymbolAddress((void**)&wol, g_wo_l);
    cudaGetSymbolAddress((void**)&qh,  g_qh);
    cudaGetSymbolAddress((void**)&ql,  g_ql);
    cudaGetSymbolAddress((void**)&kh,  g_kh);
    cudaGetSymbolAddress((void**)&kl,  g_kl);
    cudaGetSymbolAddress((void**)&vh,  g_vh);
    cudaGetSymbolAddress((void**)&vl,  g_vl);
    cudaGetSymbolAddress((void**)&ao,  g_ao);

    cumsum_kernel<<<2, 1024>>>(labels);

    split_kernel<<<(DIMN * DIMN / 4 + 255) / 256, 256>>>(wq, wqh, wql, DIMN * DIMN / 4);
    split_kernel<<<(512 * DIMN / 4 + 255) / 256, 256>>>(wk, wkh, wkl, 512 * DIMN / 4);
    split_kernel<<<(512 * DIMN / 4 + 255) / 256, 256>>>(wv, wvh, wvl, 512 * DIMN / 4);
    split_kernel<<<(DIMN * DIMN / 4 + 255) / 256, 256>>>(wo, woh, wol, DIMN * DIMN / 4);

    ln_kernel<<<ROWS, 256>>>(x, ln1w, ln1b, xnh, xnl);

    size_t gemm_smem = 2 * STAGE_B;
    cudaFuncSetAttribute(mma_gemm, cudaFuncAttributeMaxDynamicSharedMemorySize, (int)gemm_smem);

    dim3 gq(DIMN / 128, ROWS / 128);
    dim3 gkv(512 / 128, ROWS / 128);
    const float qscale = 0.08838834764831845f;   // 1/sqrt(128)

    // QKV projections with fused rope/split epilogues
    mma_gemm<<<gq, 256, gemm_smem>>>(xnh, xnl, wqh, wql, nullptr, qh, ql,
                                     freqs, 1, qscale, ROWS, DIMN, DIMN);
    mma_gemm<<<gkv, 256, gemm_smem>>>(xnh, xnl, wkh, wkl, nullptr, kh, kl,
                                      freqs, 1, 1.0f, ROWS, 512, DIMN);
    mma_gemm<<<gkv, 256, gemm_smem>>>(xnh, xnl, wvh, wvl, nullptr, vh, vl,
                                      nullptr, 2, 1.0f, ROWS, 512, DIMN);

    size_t attn_smem = 2 * QTILE + 8 * ATILE;   // 208896
    cudaFuncSetAttribute(attn_kernel, cudaFuncAttributeMaxDynamicSharedMemorySize,
                         (int)attn_smem);
    attn_kernel<<<dim3(S_LEN / 128, NH, 2), 256, attn_smem>>>();

    ln_kernel<<<ROWS, 256>>>(ao, ln2w, ln2b, xnh, xnl);
    mma_gemm<<<gq, 256, gemm_smem>>>(xnh, xnl, woh, wol, out, nullptr, nullptr,
                                     nullptr, 0, 1.0f, ROWS, DIMN, DIMN);
}